// round 3
// baseline (speedup 1.0000x reference)
#include <cuda_runtime.h>
#include <stdint.h>

#define CAP 6144
#define MAX_ROWS 16384

__device__ float g_row_loss[MAX_ROWS];
__device__ int   g_tg32;   // 1 => target buffer is int32, 0 => int64

__device__ __forceinline__ float warpMax(float v) {
    #pragma unroll
    for (int o = 16; o; o >>= 1) v = fmaxf(v, __shfl_xor_sync(0xffffffffu, v, o));
    return v;
}
__device__ __forceinline__ float warpSum(float v) {
    #pragma unroll
    for (int o = 16; o; o >>= 1) v += __shfl_xor_sync(0xffffffffu, v, o);
    return v;
}

// Detect target dtype: reading an int32 buffer as int64 yields values far
// outside [0, d) unless every odd word is zero (probability ~0 for random
// targets). Reads only the first n/2 int64 slots => in-bounds for both dtypes.
__global__ void probe_target_kernel(const long long* __restrict__ t, int n, int d) {
    __shared__ int bad;
    if (threadIdx.x == 0) bad = 0;
    __syncthreads();
    int lim = n >> 1;
    int b = 0;
    for (int i = threadIdx.x; i < lim; i += blockDim.x) {
        long long v = t[i];
        if (v < 0 || v >= (long long)d) b = 1;
    }
    if (b) bad = 1;
    __syncthreads();
    if (threadIdx.x == 0) g_tg32 = bad;
}

__global__ __launch_bounds__(512, 4)
void entmax15_loss_kernel(const float* __restrict__ input,
                          const void* __restrict__ target,
                          int n, int d) {
    __shared__ float cand[CAP];
    __shared__ float shA[16], shB[16], shC[16];
    __shared__ float s_red0, s_red1;
    __shared__ int   s_count;
    __shared__ float s_tau, s_xt;

    const int tid  = threadIdx.x;
    const int lane = tid & 31;
    const int wid  = tid >> 5;
    const int bd   = blockDim.x;
    const int nw   = bd >> 5;

    const float* in_row = input + (size_t)blockIdx.x * (size_t)d;

    if (tid == 0) {
        s_count = 0;
        long long tg = g_tg32 ? (long long)(((const int*)target)[blockIdx.x])
                              : ((const long long*)target)[blockIdx.x];
        if (tg < 0) tg = 0;
        if (tg >= d) tg = d - 1;
        s_xt = in_row[tg];
    }

    // ---- Pass 1: streaming max over the row (HBM) ----
    float vmax = -INFINITY;
    const bool al = ((((uintptr_t)in_row) & 15) == 0) && ((d & 3) == 0);
    if (al) {
        const float4* in4 = (const float4*)in_row;
        const int d4 = d >> 2;
        for (int i = tid; i < d4; i += bd) {
            float4 v = in4[i];
            vmax = fmaxf(vmax, fmaxf(fmaxf(v.x, v.y), fmaxf(v.z, v.w)));
        }
    } else {
        for (int i = tid; i < d; i += bd) vmax = fmaxf(vmax, in_row[i]);
    }
    vmax = warpMax(vmax);
    if (lane == 0) shA[wid] = vmax;
    __syncthreads();
    if (tid < 32) {
        float m2 = (tid < nw) ? shA[tid] : -INFINITY;
        m2 = warpMax(m2);
        if (tid == 0) s_red0 = m2;
    }
    __syncthreads();
    const float M = 0.5f * s_red0;           // max of X = input/2

    // ---- Pass 2: re-read row (L2-hit), compact Y = x/2 - M with Y > -1 ----
    if (al) {
        const float4* in4 = (const float4*)in_row;
        const int d4 = d >> 2;
        for (int i = tid; i < d4; i += bd) {
            float4 v = in4[i];
            float y0 = fmaf(0.5f, v.x, -M), y1 = fmaf(0.5f, v.y, -M);
            float y2 = fmaf(0.5f, v.z, -M), y3 = fmaf(0.5f, v.w, -M);
            if (y0 > -1.0f) { int id = atomicAdd(&s_count, 1); if (id < CAP) cand[id] = y0; }
            if (y1 > -1.0f) { int id = atomicAdd(&s_count, 1); if (id < CAP) cand[id] = y1; }
            if (y2 > -1.0f) { int id = atomicAdd(&s_count, 1); if (id < CAP) cand[id] = y2; }
            if (y3 > -1.0f) { int id = atomicAdd(&s_count, 1); if (id < CAP) cand[id] = y3; }
        }
    } else {
        for (int i = tid; i < d; i += bd) {
            float y = fmaf(0.5f, in_row[i], -M);
            if (y > -1.0f) { int id = atomicAdd(&s_count, 1); if (id < CAP) cand[id] = y; }
        }
    }
    __syncthreads();
    const int  count = s_count;
    const bool fit   = (count <= CAP);

    // ---- Newton on f(tau) = sum max(Y - tau, 0)^2 = 1 ; root in [-1, 0) ----
    // f convex & decreasing => Newton from tau=-1 is monotone, no overshoot.
    float tau;
    if (fit) {
        if (wid == 0) {
            float tl = -1.0f;
            #pragma unroll 1
            for (int it = 0; it < 24; ++it) {
                float s1 = 0.f, s2 = 0.f;
                for (int i = lane; i < count; i += 32) {
                    float t = cand[i] - tl;
                    if (t > 0.f) { s1 += t; s2 = fmaf(t, t, s2); }
                }
                s1 = warpSum(s1); s2 = warpSum(s2);
                tl += (s2 - 1.0f) / (2.0f * fmaxf(s1, 1e-30f));
            }
            if (lane == 0) s_tau = tl;
        }
        __syncthreads();
        tau = s_tau;
    } else {
        // Rare fallback: Newton over full row (L2 reads), block-wide.
        tau = -1.0f;
        for (int it = 0; it < 24; ++it) {
            float s1 = 0.f, s2 = 0.f;
            for (int i = tid; i < d; i += bd) {
                float t = fmaf(0.5f, in_row[i], -M) - tau;
                if (t > 0.f) { s1 += t; s2 = fmaf(t, t, s2); }
            }
            s1 = warpSum(s1); s2 = warpSum(s2);
            if (lane == 0) { shA[wid] = s1; shB[wid] = s2; }
            __syncthreads();
            if (tid < 32) {
                float a = (tid < nw) ? shA[tid] : 0.f;
                float b = (tid < nw) ? shB[tid] : 0.f;
                a = warpSum(a); b = warpSum(b);
                if (tid == 0) { s_red0 = a; s_red1 = b; }
            }
            __syncthreads();
            tau += (s_red1 - 1.0f) / (2.0f * fmaxf(s_red0, 1e-30f));
            __syncthreads();
        }
    }

    // ---- Epilogue: t3 = sum t^3, py = sum t^2*Y, p2 = sum t^2 ----
    // loss = (1 - t3)/0.75 + 2*py + 2*M*p2 - x[target]
    float t3 = 0.f, py = 0.f, p2 = 0.f;
    if (fit) {
        for (int i = tid; i < count; i += bd) {
            float y = cand[i];
            float t = y - tau;
            if (t > 0.f) { float p = t * t; t3 = fmaf(p, t, t3); py = fmaf(p, y, py); p2 += p; }
        }
    } else {
        for (int i = tid; i < d; i += bd) {
            float y = fmaf(0.5f, in_row[i], -M);
            float t = y - tau;
            if (t > 0.f) { float p = t * t; t3 = fmaf(p, t, t3); py = fmaf(p, y, py); p2 += p; }
        }
    }
    t3 = warpSum(t3); py = warpSum(py); p2 = warpSum(p2);
    if (lane == 0) { shA[wid] = t3; shB[wid] = py; shC[wid] = p2; }
    __syncthreads();
    if (tid < 32) {
        float a = (tid < nw) ? shA[tid] : 0.f;
        float b = (tid < nw) ? shB[tid] : 0.f;
        float c = (tid < nw) ? shC[tid] : 0.f;
        a = warpSum(a); b = warpSum(b); c = warpSum(c);
        if (tid == 0) {
            float omega = (1.0f - a) * (4.0f / 3.0f);
            g_row_loss[blockIdx.x] = omega + 2.0f * b + 2.0f * M * c - s_xt;
        }
    }
}

__global__ void reduce_mean_kernel(int n, float* __restrict__ out) {
    __shared__ float sh[32];
    float a = 0.f;
    for (int i = threadIdx.x; i < n; i += blockDim.x) a += g_row_loss[i];
    a = warpSum(a);
    if ((threadIdx.x & 31) == 0) sh[threadIdx.x >> 5] = a;
    __syncthreads();
    if (threadIdx.x < 32) {
        int nw = (blockDim.x + 31) >> 5;
        float v = (threadIdx.x < nw) ? sh[threadIdx.x] : 0.f;
        v = warpSum(v);
        if (threadIdx.x == 0) *out = v / (float)n;
    }
}

extern "C" void kernel_launch(void* const* d_in, const int* in_sizes, int n_in,
                              void* d_out, int out_size) {
    // Disambiguate input vs target by element count (input is the big one).
    const int i_in = (in_sizes[0] >= in_sizes[1]) ? 0 : 1;
    const int i_tg = 1 - i_in;
    const float* input  = (const float*)d_in[i_in];
    const void*  target = d_in[i_tg];
    const int n = in_sizes[i_tg];
    const int d = in_sizes[i_in] / n;

    probe_target_kernel<<<1, 256>>>((const long long*)target, n, d);
    entmax15_loss_kernel<<<n, 512>>>(input, target, n, d);
    reduce_mean_kernel<<<1, 1024>>>(n, (float*)d_out);
}